// round 1
// baseline (speedup 1.0000x reference)
#include <cuda_runtime.h>

// ButterflyTransform: x[8192,4096] fp32, W[12,2048,2,2] fp32.
// All 12 layers use identical adjacent pairing, so per pair n the full network
// is a single composed 2x2 matrix M[n] = W0[n]@W1[n]@...@W11[n] (y = x·W).
// Phase 1: compose 2048 matrices (tiny). Phase 2: one streaming pass over x.

#define BATCH   8192
#define SIZE    4096
#define NPAIRS  (SIZE / 2)        // 2048
#define LOG_N   12
#define F4_PER_ROW (SIZE / 4)     // 1024 float4 per row (2 pairs each)

// Composed matrices: (m00, m01, m10, m11) per pair. 32 KB scratch.
__device__ float4 g_M[NPAIRS];

__global__ void compose_kernel(const float* __restrict__ W) {
    int n = blockIdx.x * blockDim.x + threadIdx.x;
    if (n >= NPAIRS) return;
    const float4* Wl = reinterpret_cast<const float4*>(W);  // [l][n] -> (w00,w01,w10,w11)
    float4 m = Wl[n];  // layer 0
#pragma unroll
    for (int l = 1; l < LOG_N; l++) {
        float4 w = Wl[l * NPAIRS + n];
        // M_new = M @ W_l  (row-vector composition)
        float a = fmaf(m.x, w.x, m.y * w.z);  // new00 = m00*w00 + m01*w10
        float b = fmaf(m.x, w.y, m.y * w.w);  // new01
        float c = fmaf(m.z, w.x, m.w * w.z);  // new10
        float d = fmaf(m.z, w.y, m.w * w.w);  // new11
        m = make_float4(a, b, c, d);
    }
    g_M[n] = m;
}

#define ROWS_PER_BLOCK 16
#define TPB 256

__global__ __launch_bounds__(TPB) void apply_kernel(const float* __restrict__ x,
                                                    float* __restrict__ out) {
    // Each thread owns one float4 column slot (2 pairs) and walks ROWS_PER_BLOCK rows,
    // keeping its two composed matrices in registers.
    int col4 = blockIdx.x * TPB + threadIdx.x;        // 0..1023
    float4 mA = g_M[2 * col4];
    float4 mB = g_M[2 * col4 + 1];

    const float4* __restrict__ xin = reinterpret_cast<const float4*>(x);
    float4* __restrict__ yout = reinterpret_cast<float4*>(out);

    int row0 = blockIdx.y * ROWS_PER_BLOCK;
    long base = (long)row0 * F4_PER_ROW + col4;

#pragma unroll
    for (int r = 0; r < ROWS_PER_BLOCK; r++) {
        long idx = base + (long)r * F4_PER_ROW;
        float4 v = xin[idx];
        float4 o;
        // y_j = sum_i x_i * M[i][j]
        o.x = fmaf(v.x, mA.x, v.y * mA.z);
        o.y = fmaf(v.x, mA.y, v.y * mA.w);
        o.z = fmaf(v.z, mB.x, v.w * mB.z);
        o.w = fmaf(v.z, mB.y, v.w * mB.w);
        yout[idx] = o;
    }
}

extern "C" void kernel_launch(void* const* d_in, const int* in_sizes, int n_in,
                              void* d_out, int out_size) {
    const float* x = (const float*)d_in[0];   // [8192, 4096]
    const float* W = (const float*)d_in[1];   // [12, 2048, 2, 2]
    float* out = (float*)d_out;

    compose_kernel<<<(NPAIRS + 255) / 256, 256>>>(W);

    dim3 grid(F4_PER_ROW / TPB, BATCH / ROWS_PER_BLOCK);  // (4, 512)
    apply_kernel<<<grid, TPB>>>(x, out);
}